// round 2
// baseline (speedup 1.0000x reference)
#include <cuda_runtime.h>
#include <math.h>

// ---------------------------------------------------------------------------
// Problem constants
// ---------------------------------------------------------------------------
#define BB      2
#define SEQ     2048
#define DMODEL  2048
#define NHEAD   16
#define NKV     4
#define DHEAD   128
#define QINNER  (NHEAD * DHEAD)    // 2048
#define KVINNER (NKV * DHEAD)      // 512
#define NREP    (NHEAD / NKV)      // 4
#define MROWS   (BB * SEQ)         // 4096

// Scratch (allocation-free rule: device globals)
__device__ float g_q[MROWS * QINNER];     // [b*S + s][h*128 + d]
__device__ float g_k[MROWS * KVINNER];    // [b*S + s][kh*128 + d]
__device__ float g_v[MROWS * KVINNER];
__device__ float g_att[MROWS * QINNER];   // attention output, [b,s,h,d] flat

// ---------------------------------------------------------------------------
// GEMM: C[M,N] = A[M,K] @ W[N,K]^T + bias[N]   (torch Linear semantics)
// 128x128x16 tiles, 256 threads, 8x8 per-thread tile with 2x2 split blocking.
// ---------------------------------------------------------------------------
#define GBM 128
#define GBN 128
#define GBK 16
#define GPAD 132   // padded leading dim for smem tiles

__global__ __launch_bounds__(256)
void gemm_bias(const float* __restrict__ A, const float* __restrict__ W,
               const float* __restrict__ bias, float* __restrict__ C,
               int M, int N, int K)
{
    __shared__ float As[GBK][GPAD];
    __shared__ float Bs[GBK][GPAD];

    const int tid  = threadIdx.x;
    const int bm   = blockIdx.y * GBM;
    const int bn   = blockIdx.x * GBN;
    const int trow = tid >> 4;    // 0..15
    const int tcol = tid & 15;    // 0..15

    float acc[8][8];
#pragma unroll
    for (int i = 0; i < 8; i++)
#pragma unroll
        for (int j = 0; j < 8; j++) acc[i][j] = 0.f;

    for (int k0 = 0; k0 < K; k0 += GBK) {
#pragma unroll
        for (int it = 0; it < 2; it++) {
            int idx = tid + it * 256;       // 0..511
            int row = idx >> 2;             // 0..127
            int c4  = (idx & 3) << 2;       // 0,4,8,12
            float4 va = *(const float4*)(A + (size_t)(bm + row) * K + k0 + c4);
            As[c4 + 0][row] = va.x; As[c4 + 1][row] = va.y;
            As[c4 + 2][row] = va.z; As[c4 + 3][row] = va.w;
            float4 vb = *(const float4*)(W + (size_t)(bn + row) * K + k0 + c4);
            Bs[c4 + 0][row] = vb.x; Bs[c4 + 1][row] = vb.y;
            Bs[c4 + 2][row] = vb.z; Bs[c4 + 3][row] = vb.w;
        }
        __syncthreads();

#pragma unroll
        for (int kk = 0; kk < GBK; kk++) {
            float ra[8], rb[8];
            *(float4*)&ra[0] = *(const float4*)&As[kk][trow * 4];
            *(float4*)&ra[4] = *(const float4*)&As[kk][trow * 4 + 64];
            *(float4*)&rb[0] = *(const float4*)&Bs[kk][tcol * 4];
            *(float4*)&rb[4] = *(const float4*)&Bs[kk][tcol * 4 + 64];
#pragma unroll
            for (int i = 0; i < 8; i++)
#pragma unroll
                for (int j = 0; j < 8; j++)
                    acc[i][j] = fmaf(ra[i], rb[j], acc[i][j]);
        }
        __syncthreads();
    }

#pragma unroll
    for (int i = 0; i < 8; i++) {
        int r = bm + ((i < 4) ? (trow * 4 + i) : (64 + trow * 4 + (i - 4)));
#pragma unroll
        for (int jh = 0; jh < 2; jh++) {
            int c = bn + tcol * 4 + jh * 64;
            float4 o;
            o.x = acc[i][jh * 4 + 0] + bias[c + 0];
            o.y = acc[i][jh * 4 + 1] + bias[c + 1];
            o.z = acc[i][jh * 4 + 2] + bias[c + 2];
            o.w = acc[i][jh * 4 + 3] + bias[c + 3];
            *(float4*)(C + (size_t)r * N + c) = o;
        }
    }
}

// ---------------------------------------------------------------------------
// Flash attention (fp32, online softmax). One block = (b, h, 64 q rows).
// 256 threads as 16(ty: q) x 16(tx: k / d-slice). smem: Q^T, K^T, V, P tiles.
// ---------------------------------------------------------------------------
#define BQ   64
#define BKT  64
#define QPAD 68    // LD for transposed Q/K tiles [128][QPAD]; must be %4==0 for float4
#define VPAD 132   // LD for V tile [64][VPAD]
#define PPAD 68    // LD for P tile [64][PPAD]
#define SMEM_ATTN ((2 * 128 * QPAD + BKT * VPAD + BQ * PPAD) * (int)sizeof(float))

__global__ __launch_bounds__(256)
void attn_kernel(const int* __restrict__ mask)
{
    extern __shared__ float sm[];
    float* Qs = sm;                       // [128][QPAD]  (d-major, transposed)
    float* Ks = Qs + 128 * QPAD;          // [128][QPAD]
    float* Vs = Ks + 128 * QPAD;          // [64][VPAD]   (k-major, row)
    float* Ps = Vs + BKT * VPAD;          // [64][PPAD]

    const int tid = threadIdx.x;
    const int tx  = tid & 15;
    const int ty  = tid >> 4;
    const int q0  = blockIdx.x * BQ;
    const int bh  = blockIdx.y;
    const int b   = bh / NHEAD;
    const int h   = bh % NHEAD;
    const int kh  = h / NREP;
    const float scale = 0.08838834764831845f;   // 1/sqrt(128)

    // Load Q tile transposed: Qs[d][q]
#pragma unroll
    for (int it = 0; it < 8; it++) {
        int idx = tid + it * 256;          // 0..2047
        int r   = idx >> 5;                // 0..63  (q row)
        int c4  = (idx & 31) << 2;         // 0..124 (d)
        float4 v = *(const float4*)(g_q + (size_t)(b * SEQ + q0 + r) * QINNER + h * DHEAD + c4);
        Qs[(c4 + 0) * QPAD + r] = v.x;
        Qs[(c4 + 1) * QPAD + r] = v.y;
        Qs[(c4 + 2) * QPAD + r] = v.z;
        Qs[(c4 + 3) * QPAD + r] = v.w;
    }

    float m_i[4], l_i[4], acc[4][8];
#pragma unroll
    for (int ii = 0; ii < 4; ii++) {
        m_i[ii] = -1e30f; l_i[ii] = 0.f;
#pragma unroll
        for (int j = 0; j < 8; j++) acc[ii][j] = 0.f;
    }

    const int* mbase = mask + (size_t)b * SEQ * SEQ;

    for (int k0 = 0; k0 < SEQ; k0 += BKT) {
        __syncthreads();   // previous tile fully consumed (also covers Q stores)

        // Load K tile transposed (Ks[d][k]) and V tile row-major (Vs[k][d])
#pragma unroll
        for (int it = 0; it < 8; it++) {
            int idx = tid + it * 256;
            int r   = idx >> 5;             // key row 0..63
            int c4  = (idx & 31) << 2;      // d 0..124
            size_t goff = (size_t)(b * SEQ + k0 + r) * KVINNER + kh * DHEAD + c4;
            float4 kv = *(const float4*)(g_k + goff);
            Ks[(c4 + 0) * QPAD + r] = kv.x;
            Ks[(c4 + 1) * QPAD + r] = kv.y;
            Ks[(c4 + 2) * QPAD + r] = kv.z;
            Ks[(c4 + 3) * QPAD + r] = kv.w;
            float4 vv = *(const float4*)(g_v + goff);
            *(float4*)&Vs[r * VPAD + c4] = vv;
        }
        __syncthreads();

        // Scores: sc[ii][jj] = Q[q0+ty*4+ii] . K[k0+tx*4+jj]
        float sc[4][4];
#pragma unroll
        for (int ii = 0; ii < 4; ii++)
#pragma unroll
            for (int jj = 0; jj < 4; jj++) sc[ii][jj] = 0.f;

#pragma unroll 4
        for (int d = 0; d < DHEAD; d++) {
            float4 a  = *(const float4*)&Qs[d * QPAD + (ty << 2)];
            float4 kb = *(const float4*)&Ks[d * QPAD + (tx << 2)];
            float av[4] = {a.x, a.y, a.z, a.w};
            float kv[4] = {kb.x, kb.y, kb.z, kb.w};
#pragma unroll
            for (int ii = 0; ii < 4; ii++)
#pragma unroll
                for (int jj = 0; jj < 4; jj++)
                    sc[ii][jj] = fmaf(av[ii], kv[jj], sc[ii][jj]);
        }

        // Scale + mask + online softmax update
#pragma unroll
        for (int ii = 0; ii < 4; ii++) {
            int4 mm = *(const int4*)(mbase + (size_t)(q0 + ty * 4 + ii) * SEQ + k0 + (tx << 2));
            int mv[4] = {mm.x, mm.y, mm.z, mm.w};
#pragma unroll
            for (int jj = 0; jj < 4; jj++)
                sc[ii][jj] = mv[jj] ? sc[ii][jj] * scale : -1e30f;

            float rmax = fmaxf(fmaxf(sc[ii][0], sc[ii][1]), fmaxf(sc[ii][2], sc[ii][3]));
#pragma unroll
            for (int off = 8; off > 0; off >>= 1)
                rmax = fmaxf(rmax, __shfl_xor_sync(0xffffffffu, rmax, off));

            float mnew = fmaxf(m_i[ii], rmax);
            float corr = __expf(m_i[ii] - mnew);
            float p[4]; float rsum = 0.f;
#pragma unroll
            for (int jj = 0; jj < 4; jj++) { p[jj] = __expf(sc[ii][jj] - mnew); rsum += p[jj]; }
#pragma unroll
            for (int off = 8; off > 0; off >>= 1)
                rsum += __shfl_xor_sync(0xffffffffu, rsum, off);

            l_i[ii] = l_i[ii] * corr + rsum;
            m_i[ii] = mnew;
#pragma unroll
            for (int j = 0; j < 8; j++) acc[ii][j] *= corr;
            *(float4*)&Ps[(ty * 4 + ii) * PPAD + (tx << 2)] = make_float4(p[0], p[1], p[2], p[3]);
        }
        __syncthreads();

        // O += P @ V   (thread owns q rows ty*4..+3, d slices tx*4..+3 and +64)
#pragma unroll 2
        for (int kk = 0; kk < BKT; kk++) {
            float4 v0 = *(const float4*)&Vs[kk * VPAD + (tx << 2)];
            float4 v1 = *(const float4*)&Vs[kk * VPAD + (tx << 2) + 64];
            float vv[8] = {v0.x, v0.y, v0.z, v0.w, v1.x, v1.y, v1.z, v1.w};
#pragma unroll
            for (int ii = 0; ii < 4; ii++) {
                float p = Ps[(ty * 4 + ii) * PPAD + kk];
#pragma unroll
                for (int j = 0; j < 8; j++)
                    acc[ii][j] = fmaf(p, vv[j], acc[ii][j]);
            }
        }
    }

    // Normalize + store [b, s, h, d]
#pragma unroll
    for (int ii = 0; ii < 4; ii++) {
        float inv = (l_i[ii] > 0.f) ? (1.f / l_i[ii]) : 0.f;
        size_t base = (size_t)(b * SEQ + q0 + ty * 4 + ii) * QINNER + h * DHEAD;
        float4 o0 = make_float4(acc[ii][0] * inv, acc[ii][1] * inv, acc[ii][2] * inv, acc[ii][3] * inv);
        float4 o1 = make_float4(acc[ii][4] * inv, acc[ii][5] * inv, acc[ii][6] * inv, acc[ii][7] * inv);
        *(float4*)(g_att + base + (tx << 2))      = o0;
        *(float4*)(g_att + base + (tx << 2) + 64) = o1;
    }
}

// ---------------------------------------------------------------------------
// Launch: qkv projections -> flash attention -> output projection
// ---------------------------------------------------------------------------
extern "C" void kernel_launch(void* const* d_in, const int* in_sizes, int n_in,
                              void* d_out, int out_size)
{
    const float* x    = (const float*)d_in[0];
    const int*   mask = (const int*)  d_in[1];
    const float* Wq   = (const float*)d_in[2];
    const float* bq   = (const float*)d_in[3];
    const float* Wk   = (const float*)d_in[4];
    const float* bk   = (const float*)d_in[5];
    const float* Wv   = (const float*)d_in[6];
    const float* bv   = (const float*)d_in[7];
    const float* Wo   = (const float*)d_in[8];
    const float* bo   = (const float*)d_in[9];
    float* out = (float*)d_out;

    float *q, *k, *v, *att;
    cudaGetSymbolAddress((void**)&q,   g_q);
    cudaGetSymbolAddress((void**)&k,   g_k);
    cudaGetSymbolAddress((void**)&v,   g_v);
    cudaGetSymbolAddress((void**)&att, g_att);

    cudaFuncSetAttribute(attn_kernel, cudaFuncAttributeMaxDynamicSharedMemorySize, SMEM_ATTN);

    dim3 thr(256);
    // Q/K/V projections
    gemm_bias<<<dim3(QINNER / GBN,  MROWS / GBM), thr>>>(x, Wq, bq, q, MROWS, QINNER,  DMODEL);
    gemm_bias<<<dim3(KVINNER / GBN, MROWS / GBM), thr>>>(x, Wk, bk, k, MROWS, KVINNER, DMODEL);
    gemm_bias<<<dim3(KVINNER / GBN, MROWS / GBM), thr>>>(x, Wv, bv, v, MROWS, KVINNER, DMODEL);
    // Attention
    attn_kernel<<<dim3(SEQ / BQ, BB * NHEAD), thr, SMEM_ATTN>>>(mask);
    // Output projection
    gemm_bias<<<dim3(DMODEL / GBN, MROWS / GBM), thr>>>(att, Wo, bo, out, MROWS, DMODEL, QINNER);
}

// round 5
// speedup vs baseline: 3.2642x; 3.2642x over previous
#include <cuda_runtime.h>
#include <math.h>

// ---------------------------------------------------------------------------
// Problem constants
// ---------------------------------------------------------------------------
#define BB      2
#define SEQ     2048
#define DMODEL  2048
#define NHEAD   16
#define NKV     4
#define DHEAD   128
#define QINNER  (NHEAD * DHEAD)    // 2048
#define KVINNER (NKV * DHEAD)      // 512
#define NREP    (NHEAD / NKV)      // 4
#define MROWS   (BB * SEQ)         // 4096

// Scratch (allocation-free rule: device globals)
__device__ float g_q[MROWS * QINNER];
__device__ float g_k[MROWS * KVINNER];
__device__ float g_v[MROWS * KVINNER];
__device__ float g_att[MROWS * QINNER];

// ---------------------------------------------------------------------------
// tf32 helpers
// ---------------------------------------------------------------------------
// cvt.rna.tf32.f32 requires a .b32 destination register in PTX.
__device__ __forceinline__ float f2tf(float x) {
    unsigned y;
    asm("cvt.rna.tf32.f32 %0, %1;" : "=r"(y) : "f"(x));
    return __uint_as_float(y);
}
__device__ __forceinline__ unsigned f2tfu(float x) {
    unsigned y;
    asm("cvt.rna.tf32.f32 %0, %1;" : "=r"(y) : "f"(x));
    return y;
}

// D += A(16x8) * B(8x8), tf32 inputs, fp32 accum
__device__ __forceinline__ void mma8(float* d, const unsigned* a, const unsigned* b) {
    asm("mma.sync.aligned.m16n8k8.row.col.f32.tf32.tf32.f32 "
        "{%0,%1,%2,%3},{%4,%5,%6,%7},{%8,%9},{%0,%1,%2,%3};"
        : "+f"(d[0]), "+f"(d[1]), "+f"(d[2]), "+f"(d[3])
        : "r"(a[0]), "r"(a[1]), "r"(a[2]), "r"(a[3]), "r"(b[0]), "r"(b[1]));
}

// ---------------------------------------------------------------------------
// tf32 GEMM: C[M,N] = A[M,K] @ W[N,K]^T + bias[N]
// 128x128x32 tiles, 8 warps (2x4), each warp 64x32 via 4x4 m16n8k8 tiles.
// ---------------------------------------------------------------------------
#define TBM 128
#define TBN 128
#define TBK 32
#define TPAD 36    // smem leading dim (floats); 36 % 32 = 4 -> conflict-free frags

__global__ __launch_bounds__(256, 2)
void gemm_tf32(const float* __restrict__ A, const float* __restrict__ W,
               const float* __restrict__ bias, float* __restrict__ C,
               int M, int N, int K)
{
    __shared__ float As[TBM][TPAD];
    __shared__ float Ws[TBN][TPAD];

    const int tid  = threadIdx.x;
    const int lane = tid & 31;
    const int wid  = tid >> 5;
    const int gID  = lane >> 2;   // 0..7
    const int tig  = lane & 3;    // 0..3
    const int wm   = (wid & 1) * 64;
    const int wn   = (wid >> 1) * 32;
    const int bm   = blockIdx.y * TBM;
    const int bn   = blockIdx.x * TBN;

    float acc[4][4][4];
#pragma unroll
    for (int mi = 0; mi < 4; mi++)
#pragma unroll
        for (int ni = 0; ni < 4; ni++)
#pragma unroll
            for (int j = 0; j < 4; j++) acc[mi][ni][j] = 0.f;

    for (int k0 = 0; k0 < K; k0 += TBK) {
#pragma unroll
        for (int it = 0; it < 4; it++) {
            int idx = tid + it * 256;     // 0..1023
            int row = idx >> 3;           // 0..127
            int c4  = (idx & 7) << 2;     // 0..28
            float4 va = *(const float4*)(A + (size_t)(bm + row) * K + k0 + c4);
            va.x = f2tf(va.x); va.y = f2tf(va.y); va.z = f2tf(va.z); va.w = f2tf(va.w);
            *(float4*)&As[row][c4] = va;
            float4 vb = *(const float4*)(W + (size_t)(bn + row) * K + k0 + c4);
            vb.x = f2tf(vb.x); vb.y = f2tf(vb.y); vb.z = f2tf(vb.z); vb.w = f2tf(vb.w);
            *(float4*)&Ws[row][c4] = vb;
        }
        __syncthreads();

#pragma unroll
        for (int ks = 0; ks < 4; ks++) {
            unsigned af[4][4], bf[4][2];
#pragma unroll
            for (int mi = 0; mi < 4; mi++) {
                int r = wm + mi * 16 + gID;
                af[mi][0] = __float_as_uint(As[r]    [ks * 8 + tig]);
                af[mi][1] = __float_as_uint(As[r + 8][ks * 8 + tig]);
                af[mi][2] = __float_as_uint(As[r]    [ks * 8 + tig + 4]);
                af[mi][3] = __float_as_uint(As[r + 8][ks * 8 + tig + 4]);
            }
#pragma unroll
            for (int ni = 0; ni < 4; ni++) {
                int c = wn + ni * 8 + gID;
                bf[ni][0] = __float_as_uint(Ws[c][ks * 8 + tig]);
                bf[ni][1] = __float_as_uint(Ws[c][ks * 8 + tig + 4]);
            }
#pragma unroll
            for (int mi = 0; mi < 4; mi++)
#pragma unroll
                for (int ni = 0; ni < 4; ni++)
                    mma8(acc[mi][ni], af[mi], bf[ni]);
        }
        __syncthreads();
    }

#pragma unroll
    for (int mi = 0; mi < 4; mi++) {
        int r = bm + wm + mi * 16 + gID;
#pragma unroll
        for (int ni = 0; ni < 4; ni++) {
            int c = bn + wn + ni * 8 + 2 * tig;
            float2 bv = *(const float2*)(bias + c);
            *(float2*)(C + (size_t)r * N + c) =
                make_float2(acc[mi][ni][0] + bv.x, acc[mi][ni][1] + bv.y);
            *(float2*)(C + (size_t)(r + 8) * N + c) =
                make_float2(acc[mi][ni][2] + bv.x, acc[mi][ni][3] + bv.y);
        }
    }
}

// ---------------------------------------------------------------------------
// tf32 flash attention. BQ=128 q rows/block, BK=64 keys/tile, 8 warps.
// Warp w owns q rows 16w..16w+15 (softmax reductions stay in 4-lane groups).
// Q fragments live in registers; K/V stream through smem; P via smem (warp-
// private region, __syncwarp only).
// ---------------------------------------------------------------------------
#define ABQ  128
#define ABK  64
#define KPAD 132   // % 32 == 4 -> conflict-free K b-frags
#define VPAD 136   // % 32 == 8 -> conflict-free V b-frags
#define PPAD 68    // % 32 == 4 -> conflict-free P a-frags
#define SMEM_ATTN ((ABK * KPAD + ABK * VPAD + ABQ * PPAD) * (int)sizeof(float))

__global__ __launch_bounds__(256, 1)
void attn_tf32(const int* __restrict__ mask)
{
    extern __shared__ float sm[];
    float* Ks = sm;                   // [64][KPAD]  (key-major)
    float* Vs = Ks + ABK * KPAD;      // [64][VPAD]  (key-major)
    float* Ps = Vs + ABK * VPAD;      // [128][PPAD]

    const int tid  = threadIdx.x;
    const int lane = tid & 31;
    const int wid  = tid >> 5;        // 0..7
    const int gID  = lane >> 2;       // 0..7
    const int tig  = lane & 3;        // 0..3
    const int q0   = blockIdx.x * ABQ;
    const int bh   = blockIdx.y;
    const int b    = bh >> 4;
    const int h    = bh & 15;
    const int kh   = h >> 2;
    const float scale = 0.08838834764831845f;   // 1/sqrt(128)

    // ---- Q fragments in registers (rows qr0 = q0+16w+gID, qr0+8) ----
    const int qr0 = q0 + wid * 16 + gID;
    const float* qb0 = g_q + (size_t)(b * SEQ + qr0) * QINNER + h * DHEAD;
    const float* qb1 = qb0 + 8 * QINNER;
    unsigned qa[16][4];
#pragma unroll
    for (int ks = 0; ks < 16; ks++) {
        qa[ks][0] = f2tfu(qb0[ks * 8 + tig]);
        qa[ks][1] = f2tfu(qb1[ks * 8 + tig]);
        qa[ks][2] = f2tfu(qb0[ks * 8 + tig + 4]);
        qa[ks][3] = f2tfu(qb1[ks * 8 + tig + 4]);
    }

    float o[16][4];
#pragma unroll
    for (int n = 0; n < 16; n++)
#pragma unroll
        for (int j = 0; j < 4; j++) o[n][j] = 0.f;
    float m0 = -1e30f, m1 = -1e30f, l0 = 0.f, l1 = 0.f;

    const int* mrow0 = mask + (size_t)b * SEQ * SEQ + (size_t)qr0 * SEQ;
    const int* mrow1 = mrow0 + 8 * SEQ;

    float* prow0 = Ps + (wid * 16 + gID) * PPAD;
    float* prow1 = prow0 + 8 * PPAD;

    for (int k0 = 0; k0 < SEQ; k0 += ABK) {
        __syncthreads();   // smem tiles from previous iter fully consumed
        // ---- load K/V tiles (tf32-converted) ----
#pragma unroll
        for (int it = 0; it < 8; it++) {
            int idx = tid + it * 256;       // 0..2047
            int r   = idx >> 5;             // 0..63
            int c4  = (idx & 31) << 2;      // 0..124
            size_t goff = (size_t)(b * SEQ + k0 + r) * KVINNER + kh * DHEAD + c4;
            float4 kv = *(const float4*)(g_k + goff);
            kv.x = f2tf(kv.x); kv.y = f2tf(kv.y); kv.z = f2tf(kv.z); kv.w = f2tf(kv.w);
            *(float4*)&Ks[r * KPAD + c4] = kv;
            float4 vv = *(const float4*)(g_v + goff);
            vv.x = f2tf(vv.x); vv.y = f2tf(vv.y); vv.z = f2tf(vv.z); vv.w = f2tf(vv.w);
            *(float4*)&Vs[r * VPAD + c4] = vv;
        }
        __syncthreads();

        // ---- S = Q @ K^T  (8 n-tiles of 8 keys, 16 k-steps of d) ----
        float s[8][4];
#pragma unroll
        for (int ni = 0; ni < 8; ni++)
#pragma unroll
            for (int j = 0; j < 4; j++) s[ni][j] = 0.f;

#pragma unroll
        for (int ks = 0; ks < 16; ks++) {
#pragma unroll
            for (int ni = 0; ni < 8; ni++) {
                unsigned bf[2];
                const float* kp = &Ks[(ni * 8 + gID) * KPAD + ks * 8 + tig];
                bf[0] = __float_as_uint(kp[0]);
                bf[1] = __float_as_uint(kp[4]);
                mma8(s[ni], qa[ks], bf);
            }
        }

        // ---- scale + mask + online softmax ----
        float nm0 = m0, nm1 = m1;
#pragma unroll
        for (int ni = 0; ni < 8; ni++) {
            int cc = k0 + ni * 8 + 2 * tig;
            int2 mm0 = *(const int2*)(mrow0 + cc);
            int2 mm1 = *(const int2*)(mrow1 + cc);
            s[ni][0] = mm0.x ? s[ni][0] * scale : -1e30f;
            s[ni][1] = mm0.y ? s[ni][1] * scale : -1e30f;
            s[ni][2] = mm1.x ? s[ni][2] * scale : -1e30f;
            s[ni][3] = mm1.y ? s[ni][3] * scale : -1e30f;
            nm0 = fmaxf(nm0, fmaxf(s[ni][0], s[ni][1]));
            nm1 = fmaxf(nm1, fmaxf(s[ni][2], s[ni][3]));
        }
        nm0 = fmaxf(nm0, __shfl_xor_sync(0xffffffffu, nm0, 1));
        nm0 = fmaxf(nm0, __shfl_xor_sync(0xffffffffu, nm0, 2));
        nm1 = fmaxf(nm1, __shfl_xor_sync(0xffffffffu, nm1, 1));
        nm1 = fmaxf(nm1, __shfl_xor_sync(0xffffffffu, nm1, 2));

        float corr0 = __expf(m0 - nm0);
        float corr1 = __expf(m1 - nm1);
        m0 = nm0; m1 = nm1;

        float rs0 = 0.f, rs1 = 0.f;
#pragma unroll
        for (int ni = 0; ni < 8; ni++) {
            s[ni][0] = (s[ni][0] > -1e29f) ? __expf(s[ni][0] - m0) : 0.f;
            s[ni][1] = (s[ni][1] > -1e29f) ? __expf(s[ni][1] - m0) : 0.f;
            s[ni][2] = (s[ni][2] > -1e29f) ? __expf(s[ni][2] - m1) : 0.f;
            s[ni][3] = (s[ni][3] > -1e29f) ? __expf(s[ni][3] - m1) : 0.f;
            rs0 += s[ni][0] + s[ni][1];
            rs1 += s[ni][2] + s[ni][3];
        }
        rs0 += __shfl_xor_sync(0xffffffffu, rs0, 1);
        rs0 += __shfl_xor_sync(0xffffffffu, rs0, 2);
        rs1 += __shfl_xor_sync(0xffffffffu, rs1, 1);
        rs1 += __shfl_xor_sync(0xffffffffu, rs1, 2);
        l0 = l0 * corr0 + rs0;
        l1 = l1 * corr1 + rs1;

#pragma unroll
        for (int n = 0; n < 16; n++) {
            o[n][0] *= corr0; o[n][1] *= corr0;
            o[n][2] *= corr1; o[n][3] *= corr1;
        }

        // ---- stash P (tf32) in warp-private smem rows ----
#pragma unroll
        for (int ni = 0; ni < 8; ni++) {
            *(float2*)(prow0 + ni * 8 + 2 * tig) = make_float2(f2tf(s[ni][0]), f2tf(s[ni][1]));
            *(float2*)(prow1 + ni * 8 + 2 * tig) = make_float2(f2tf(s[ni][2]), f2tf(s[ni][3]));
        }
        __syncwarp();

        // ---- O += P @ V  (16 n-tiles of d, 8 k-steps of keys) ----
#pragma unroll
        for (int ks2 = 0; ks2 < 8; ks2++) {
            unsigned pa[4];
            pa[0] = __float_as_uint(prow0[ks2 * 8 + tig]);
            pa[1] = __float_as_uint(prow1[ks2 * 8 + tig]);
            pa[2] = __float_as_uint(prow0[ks2 * 8 + tig + 4]);
            pa[3] = __float_as_uint(prow1[ks2 * 8 + tig + 4]);
#pragma unroll
            for (int ni = 0; ni < 16; ni++) {
                unsigned bf[2];
                const float* vp = &Vs[(ks2 * 8 + tig) * VPAD + ni * 8 + gID];
                bf[0] = __float_as_uint(vp[0]);
                bf[1] = __float_as_uint(vp[4 * VPAD]);
                mma8(o[ni], pa, bf);
            }
        }
    }

    // ---- normalize + store [b,s,h,d] ----
    float inv0 = (l0 > 0.f) ? (1.f / l0) : 0.f;
    float inv1 = (l1 > 0.f) ? (1.f / l1) : 0.f;
    float* ob0 = g_att + (size_t)(b * SEQ + qr0) * QINNER + h * DHEAD;
    float* ob1 = ob0 + 8 * QINNER;
#pragma unroll
    for (int ni = 0; ni < 16; ni++) {
        *(float2*)(ob0 + ni * 8 + 2 * tig) = make_float2(o[ni][0] * inv0, o[ni][1] * inv0);
        *(float2*)(ob1 + ni * 8 + 2 * tig) = make_float2(o[ni][2] * inv1, o[ni][3] * inv1);
    }
}

// ---------------------------------------------------------------------------
// Launch
// ---------------------------------------------------------------------------
extern "C" void kernel_launch(void* const* d_in, const int* in_sizes, int n_in,
                              void* d_out, int out_size)
{
    const float* x    = (const float*)d_in[0];
    const int*   mask = (const int*)  d_in[1];
    const float* Wq   = (const float*)d_in[2];
    const float* bq   = (const float*)d_in[3];
    const float* Wk   = (const float*)d_in[4];
    const float* bk   = (const float*)d_in[5];
    const float* Wv   = (const float*)d_in[6];
    const float* bv   = (const float*)d_in[7];
    const float* Wo   = (const float*)d_in[8];
    const float* bo   = (const float*)d_in[9];
    float* out = (float*)d_out;

    float *q, *k, *v, *att;
    cudaGetSymbolAddress((void**)&q,   g_q);
    cudaGetSymbolAddress((void**)&k,   g_k);
    cudaGetSymbolAddress((void**)&v,   g_v);
    cudaGetSymbolAddress((void**)&att, g_att);

    cudaFuncSetAttribute(attn_tf32, cudaFuncAttributeMaxDynamicSharedMemorySize, SMEM_ATTN);

    dim3 thr(256);
    gemm_tf32<<<dim3(QINNER / TBN,  MROWS / TBM), thr>>>(x, Wq, bq, q, MROWS, QINNER,  DMODEL);
    gemm_tf32<<<dim3(KVINNER / TBN, MROWS / TBM), thr>>>(x, Wk, bk, k, MROWS, KVINNER, DMODEL);
    gemm_tf32<<<dim3(KVINNER / TBN, MROWS / TBM), thr>>>(x, Wv, bv, v, MROWS, KVINNER, DMODEL);
    attn_tf32<<<dim3(SEQ / ABQ, BB * NHEAD), thr, SMEM_ATTN>>>(mask);
    gemm_tf32<<<dim3(DMODEL / TBN, MROWS / TBM), thr>>>(att, Wo, bo, out, MROWS, DMODEL, QINNER);
}

// round 6
// speedup vs baseline: 3.6915x; 1.1309x over previous
#include <cuda_runtime.h>
#include <math.h>

// ---------------------------------------------------------------------------
// Problem constants
// ---------------------------------------------------------------------------
#define BB      2
#define SEQ     2048
#define DMODEL  2048
#define NHEAD   16
#define NKV     4
#define DHEAD   128
#define QINNER  (NHEAD * DHEAD)    // 2048
#define KVINNER (NKV * DHEAD)      // 512
#define NREP    (NHEAD / NKV)      // 4
#define MROWS   (BB * SEQ)         // 4096

// Scratch (allocation-free rule: device globals)
__device__ float g_q[MROWS * QINNER];
__device__ float g_k[MROWS * KVINNER];
__device__ float g_v[MROWS * KVINNER];
__device__ float g_att[MROWS * QINNER];

// ---------------------------------------------------------------------------
// tf32 helpers
// ---------------------------------------------------------------------------
__device__ __forceinline__ float f2tf(float x) {
    unsigned y;
    asm("cvt.rna.tf32.f32 %0, %1;" : "=r"(y) : "f"(x));
    return __uint_as_float(y);
}
__device__ __forceinline__ unsigned f2tfu(float x) {
    unsigned y;
    asm("cvt.rna.tf32.f32 %0, %1;" : "=r"(y) : "f"(x));
    return y;
}

// D += A(16x8) * B(8x8), tf32 inputs, fp32 accum
__device__ __forceinline__ void mma8(float* d, const unsigned* a, const unsigned* b) {
    asm("mma.sync.aligned.m16n8k8.row.col.f32.tf32.tf32.f32 "
        "{%0,%1,%2,%3},{%4,%5,%6,%7},{%8,%9},{%0,%1,%2,%3};"
        : "+f"(d[0]), "+f"(d[1]), "+f"(d[2]), "+f"(d[3])
        : "r"(a[0]), "r"(a[1]), "r"(a[2]), "r"(a[3]), "r"(b[0]), "r"(b[1]));
}

// ---------------------------------------------------------------------------
// tf32 GEMM body: C[M,N] = A[M,K] @ W[N,K]^T + bias[N]
// 128x128x32 tiles, 8 warps (2x4), each warp 64x32 via 4x4 m16n8k8 tiles.
// ---------------------------------------------------------------------------
#define TBM 128
#define TBN 128
#define TBK 32
#define TPAD 36    // smem leading dim; 36 % 32 = 4 -> conflict-free frags

__device__ __forceinline__
void gemm_body(const float* __restrict__ A, const float* __restrict__ W,
               const float* __restrict__ bias, float* __restrict__ C,
               int N, int K, int bm, int bn,
               float (*As)[TPAD], float (*Ws)[TPAD])
{
    const int tid  = threadIdx.x;
    const int lane = tid & 31;
    const int wid  = tid >> 5;
    const int gID  = lane >> 2;
    const int tig  = lane & 3;
    const int wm   = (wid & 1) * 64;
    const int wn   = (wid >> 1) * 32;

    float acc[4][4][4];
#pragma unroll
    for (int mi = 0; mi < 4; mi++)
#pragma unroll
        for (int ni = 0; ni < 4; ni++)
#pragma unroll
            for (int j = 0; j < 4; j++) acc[mi][ni][j] = 0.f;

    for (int k0 = 0; k0 < K; k0 += TBK) {
#pragma unroll
        for (int it = 0; it < 4; it++) {
            int idx = tid + it * 256;
            int row = idx >> 3;
            int c4  = (idx & 7) << 2;
            float4 va = *(const float4*)(A + (size_t)(bm + row) * K + k0 + c4);
            va.x = f2tf(va.x); va.y = f2tf(va.y); va.z = f2tf(va.z); va.w = f2tf(va.w);
            *(float4*)&As[row][c4] = va;
            float4 vb = *(const float4*)(W + (size_t)(bn + row) * K + k0 + c4);
            vb.x = f2tf(vb.x); vb.y = f2tf(vb.y); vb.z = f2tf(vb.z); vb.w = f2tf(vb.w);
            *(float4*)&Ws[row][c4] = vb;
        }
        __syncthreads();

#pragma unroll
        for (int ks = 0; ks < 4; ks++) {
            unsigned af[4][4], bf[4][2];
#pragma unroll
            for (int mi = 0; mi < 4; mi++) {
                int r = wm + mi * 16 + gID;
                af[mi][0] = __float_as_uint(As[r]    [ks * 8 + tig]);
                af[mi][1] = __float_as_uint(As[r + 8][ks * 8 + tig]);
                af[mi][2] = __float_as_uint(As[r]    [ks * 8 + tig + 4]);
                af[mi][3] = __float_as_uint(As[r + 8][ks * 8 + tig + 4]);
            }
#pragma unroll
            for (int ni = 0; ni < 4; ni++) {
                int c = wn + ni * 8 + gID;
                bf[ni][0] = __float_as_uint(Ws[c][ks * 8 + tig]);
                bf[ni][1] = __float_as_uint(Ws[c][ks * 8 + tig + 4]);
            }
#pragma unroll
            for (int mi = 0; mi < 4; mi++)
#pragma unroll
                for (int ni = 0; ni < 4; ni++)
                    mma8(acc[mi][ni], af[mi], bf[ni]);
        }
        __syncthreads();
    }

#pragma unroll
    for (int mi = 0; mi < 4; mi++) {
        int r = bm + wm + mi * 16 + gID;
#pragma unroll
        for (int ni = 0; ni < 4; ni++) {
            int c = bn + wn + ni * 8 + 2 * tig;
            float2 bv = *(const float2*)(bias + c);
            *(float2*)(C + (size_t)r * N + c) =
                make_float2(acc[mi][ni][0] + bv.x, acc[mi][ni][1] + bv.y);
            *(float2*)(C + (size_t)(r + 8) * N + c) =
                make_float2(acc[mi][ni][2] + bv.x, acc[mi][ni][3] + bv.y);
        }
    }
}

// Fused QKV projection: blockIdx.x 0..15 -> Q cols, 16..19 -> K, 20..23 -> V
__global__ __launch_bounds__(256, 2)
void qkv_tf32(const float* __restrict__ x,
              const float* __restrict__ Wq, const float* __restrict__ bq,
              const float* __restrict__ Wk, const float* __restrict__ bk,
              const float* __restrict__ Wv, const float* __restrict__ bv,
              float* __restrict__ qp, float* __restrict__ kp, float* __restrict__ vp)
{
    __shared__ float As[TBM][TPAD];
    __shared__ float Ws[TBN][TPAD];
    int bx = blockIdx.x;
    const float *W, *bias; float* C; int N, bn;
    if (bx < 16)      { W = Wq; bias = bq; C = qp; N = QINNER;  bn = bx * 128; }
    else if (bx < 20) { W = Wk; bias = bk; C = kp; N = KVINNER; bn = (bx - 16) * 128; }
    else              { W = Wv; bias = bv; C = vp; N = KVINNER; bn = (bx - 20) * 128; }
    gemm_body(x, W, bias, C, N, DMODEL, blockIdx.y * TBM, bn, As, Ws);
}

__global__ __launch_bounds__(256, 2)
void oproj_tf32(const float* __restrict__ A, const float* __restrict__ Wo,
                const float* __restrict__ bo, float* __restrict__ C)
{
    __shared__ float As[TBM][TPAD];
    __shared__ float Ws[TBN][TPAD];
    gemm_body(A, Wo, bo, C, DMODEL, QINNER, blockIdx.y * TBM, blockIdx.x * TBN, As, Ws);
}

// ---------------------------------------------------------------------------
// tf32 flash attention with fragment-major K/V smem.
// BQ=128 q rows/block, BK=64 keys/tile, 8 warps; warp w owns q rows 16w..16w+15.
// K frags: Kf[ks(0..15)][nip(0..3)][lane^(ks&7)] uint4 =
//          {K[2nip*8+gID][ks*8+tig], K[...][ks*8+tig+4], same for 2nip+1}
// V frags: Vf[ks2(0..7)][nip(0..7)][lane^nip] uint4 =
//          {V[ks2*8+tig][2nip*8+gID], V[ks2*8+tig+4][...], same for 2nip+1}
// ---------------------------------------------------------------------------
#define ABQ  128
#define ABK  64
#define PPAD 68
#define KF_U4 (16 * 4 * 32)     // 2048 uint4 = 32KB
#define VF_U4 (8 * 8 * 32)      // 2048 uint4 = 32KB
#define SMEM_ATTN ((KF_U4 + VF_U4) * 16 + ABQ * PPAD * (int)sizeof(float))

__global__ __launch_bounds__(256, 1)
void attn_tf32(const int* __restrict__ mask)
{
    extern __shared__ float sm[];
    uint4* Kf = (uint4*)sm;
    uint4* Vf = Kf + KF_U4;
    float* Kff = (float*)Kf;
    float* Vff = (float*)Vf;
    float* Ps  = (float*)(Vf + VF_U4);   // [128][PPAD]

    const int tid  = threadIdx.x;
    const int lane = tid & 31;
    const int wid  = tid >> 5;
    const int gID  = lane >> 2;
    const int tig  = lane & 3;
    const int q0   = blockIdx.x * ABQ;
    const int bh   = blockIdx.y;
    const int b    = bh >> 4;
    const int h    = bh & 15;
    const int kh   = h >> 2;
    const float scale = 0.08838834764831845f;   // 1/sqrt(128)

    // ---- Q fragments in registers (rows qr0 = q0+16w+gID, qr0+8) ----
    const int qr0 = q0 + wid * 16 + gID;
    const float* qb0 = g_q + (size_t)(b * SEQ + qr0) * QINNER + h * DHEAD;
    const float* qb1 = qb0 + 8 * QINNER;
    unsigned qa[16][4];
#pragma unroll
    for (int ks = 0; ks < 16; ks++) {
        qa[ks][0] = f2tfu(qb0[ks * 8 + tig]);
        qa[ks][1] = f2tfu(qb1[ks * 8 + tig]);
        qa[ks][2] = f2tfu(qb0[ks * 8 + tig + 4]);
        qa[ks][3] = f2tfu(qb1[ks * 8 + tig + 4]);
    }

    float o[16][4];
#pragma unroll
    for (int n = 0; n < 16; n++)
#pragma unroll
        for (int j = 0; j < 4; j++) o[n][j] = 0.f;
    float m0 = -1e30f, m1 = -1e30f, l0 = 0.f, l1 = 0.f;

    const int* mrow0 = mask + (size_t)b * SEQ * SEQ + (size_t)qr0 * SEQ;
    const int* mrow1 = mrow0 + 8 * SEQ;

    float* prow0 = Ps + (wid * 16 + gID) * PPAD;
    float* prow1 = prow0 + 8 * PPAD;

    // fill-time per-thread constants (within a warp, key row r = wid + it*8)
    const int f_ks   = lane >> 1;        // K: d-group, V: n-group index base
    const int f_half = lane & 1;         // K: d-half
    const int f_ni   = lane >> 1;        // V: ni = c>>3
    const int f_nip  = lane >> 2;        // V: nip

    for (int k0 = 0; k0 < SEQ; k0 += ABK) {
        __syncthreads();
        // ---- fill K/V fragment-major tiles (tf32-converted) ----
#pragma unroll
        for (int it = 0; it < 8; it++) {
            int r = wid + it * 8;                 // key row 0..63
            size_t goff = (size_t)(b * SEQ + k0 + r) * KVINNER + kh * DHEAD + lane * 4;
            // K element (r, c=4*lane+j): ni=r>>3 gID=r&7 ; ks=f_ks tig=j half=f_half
            {
                int ni  = r >> 3, gK = r & 7, nip = ni >> 1;
                int kbase = ((f_ks * 4 + nip) * 32) * 4 + f_half + ((ni & 1) << 1);
                int sw = f_ks & 7;
                float4 kv = *(const float4*)(g_k + goff);
                Kff[kbase + (((gK << 2) | 0) ^ sw) * 4] = f2tf(kv.x);
                Kff[kbase + (((gK << 2) | 1) ^ sw) * 4] = f2tf(kv.y);
                Kff[kbase + (((gK << 2) | 2) ^ sw) * 4] = f2tf(kv.z);
                Kff[kbase + (((gK << 2) | 3) ^ sw) * 4] = f2tf(kv.w);
            }
            // V element (r, c=4*lane+j): ks2=r>>3 tigv=r&3 halfv=(r>>2)&1 ;
            //                            ni=f_ni gIDv=((lane&1)<<2)+j
            {
                int ks2 = r >> 3, tigv = r & 3, halfv = (r >> 2) & 1;
                int vbase = ((ks2 * 8 + f_nip) * 32) * 4 + halfv + ((f_ni & 1) << 1);
                int sw = f_nip & 7;
                int g0 = (lane & 1) << 2;
                float4 vv = *(const float4*)(g_v + goff);
                Vff[vbase + (((( g0 | 0) << 2) | tigv) ^ sw) * 4] = f2tf(vv.x);
                Vff[vbase + ((((g0 | 1) << 2) | tigv) ^ sw) * 4] = f2tf(vv.y);
                Vff[vbase + ((((g0 | 2) << 2) | tigv) ^ sw) * 4] = f2tf(vv.z);
                Vff[vbase + ((((g0 | 3) << 2) | tigv) ^ sw) * 4] = f2tf(vv.w);
            }
        }
        __syncthreads();

        // ---- S = Q @ K^T ----
        float s[8][4];
#pragma unroll
        for (int ni = 0; ni < 8; ni++)
#pragma unroll
            for (int j = 0; j < 4; j++) s[ni][j] = 0.f;

#pragma unroll
        for (int ks = 0; ks < 16; ks++) {
            int lsw = lane ^ (ks & 7);
#pragma unroll
            for (int nip = 0; nip < 4; nip++) {
                uint4 kf = Kf[(ks * 4 + nip) * 32 + lsw];
                unsigned bfe[2] = {kf.x, kf.y};
                unsigned bfo[2] = {kf.z, kf.w};
                mma8(s[2 * nip],     qa[ks], bfe);
                mma8(s[2 * nip + 1], qa[ks], bfo);
            }
        }

        // ---- scale + mask + online softmax ----
        float nm0 = m0, nm1 = m1;
#pragma unroll
        for (int ni = 0; ni < 8; ni++) {
            int cc = k0 + ni * 8 + 2 * tig;
            int2 mm0 = *(const int2*)(mrow0 + cc);
            int2 mm1 = *(const int2*)(mrow1 + cc);
            s[ni][0] = mm0.x ? s[ni][0] * scale : -1e30f;
            s[ni][1] = mm0.y ? s[ni][1] * scale : -1e30f;
            s[ni][2] = mm1.x ? s[ni][2] * scale : -1e30f;
            s[ni][3] = mm1.y ? s[ni][3] * scale : -1e30f;
            nm0 = fmaxf(nm0, fmaxf(s[ni][0], s[ni][1]));
            nm1 = fmaxf(nm1, fmaxf(s[ni][2], s[ni][3]));
        }
        nm0 = fmaxf(nm0, __shfl_xor_sync(0xffffffffu, nm0, 1));
        nm0 = fmaxf(nm0, __shfl_xor_sync(0xffffffffu, nm0, 2));
        nm1 = fmaxf(nm1, __shfl_xor_sync(0xffffffffu, nm1, 1));
        nm1 = fmaxf(nm1, __shfl_xor_sync(0xffffffffu, nm1, 2));

        float corr0 = __expf(m0 - nm0);
        float corr1 = __expf(m1 - nm1);
        m0 = nm0; m1 = nm1;

        float rs0 = 0.f, rs1 = 0.f;
#pragma unroll
        for (int ni = 0; ni < 8; ni++) {
            s[ni][0] = (s[ni][0] > -1e29f) ? __expf(s[ni][0] - m0) : 0.f;
            s[ni][1] = (s[ni][1] > -1e29f) ? __expf(s[ni][1] - m0) : 0.f;
            s[ni][2] = (s[ni][2] > -1e29f) ? __expf(s[ni][2] - m1) : 0.f;
            s[ni][3] = (s[ni][3] > -1e29f) ? __expf(s[ni][3] - m1) : 0.f;
            rs0 += s[ni][0] + s[ni][1];
            rs1 += s[ni][2] + s[ni][3];
        }
        rs0 += __shfl_xor_sync(0xffffffffu, rs0, 1);
        rs0 += __shfl_xor_sync(0xffffffffu, rs0, 2);
        rs1 += __shfl_xor_sync(0xffffffffu, rs1, 1);
        rs1 += __shfl_xor_sync(0xffffffffu, rs1, 2);
        l0 = l0 * corr0 + rs0;
        l1 = l1 * corr1 + rs1;

#pragma unroll
        for (int n = 0; n < 16; n++) {
            o[n][0] *= corr0; o[n][1] *= corr0;
            o[n][2] *= corr1; o[n][3] *= corr1;
        }

        // ---- stash P (tf32) in warp-private smem rows ----
#pragma unroll
        for (int ni = 0; ni < 8; ni++) {
            *(float2*)(prow0 + ni * 8 + 2 * tig) = make_float2(f2tf(s[ni][0]), f2tf(s[ni][1]));
            *(float2*)(prow1 + ni * 8 + 2 * tig) = make_float2(f2tf(s[ni][2]), f2tf(s[ni][3]));
        }
        __syncwarp();

        // ---- O += P @ V ----
#pragma unroll
        for (int ks2 = 0; ks2 < 8; ks2++) {
            unsigned pa[4];
            pa[0] = __float_as_uint(prow0[ks2 * 8 + tig]);
            pa[1] = __float_as_uint(prow1[ks2 * 8 + tig]);
            pa[2] = __float_as_uint(prow0[ks2 * 8 + tig + 4]);
            pa[3] = __float_as_uint(prow1[ks2 * 8 + tig + 4]);
#pragma unroll
            for (int nip = 0; nip < 8; nip++) {
                uint4 vf = Vf[(ks2 * 8 + nip) * 32 + (lane ^ nip)];
                unsigned bfe[2] = {vf.x, vf.y};
                unsigned bfo[2] = {vf.z, vf.w};
                mma8(o[2 * nip],     pa, bfe);
                mma8(o[2 * nip + 1], pa, bfo);
            }
        }
    }

    // ---- normalize + store [b,s,h,d] ----
    float inv0 = (l0 > 0.f) ? (1.f / l0) : 0.f;
    float inv1 = (l1 > 0.f) ? (1.f / l1) : 0.f;
    float* ob0 = g_att + (size_t)(b * SEQ + qr0) * QINNER + h * DHEAD;
    float* ob1 = ob0 + 8 * QINNER;
#pragma unroll
    for (int ni = 0; ni < 16; ni++) {
        *(float2*)(ob0 + ni * 8 + 2 * tig) = make_float2(o[ni][0] * inv0, o[ni][1] * inv0);
        *(float2*)(ob1 + ni * 8 + 2 * tig) = make_float2(o[ni][2] * inv1, o[ni][3] * inv1);
    }
}

// ---------------------------------------------------------------------------
// Launch
// ---------------------------------------------------------------------------
extern "C" void kernel_launch(void* const* d_in, const int* in_sizes, int n_in,
                              void* d_out, int out_size)
{
    const float* x    = (const float*)d_in[0];
    const int*   mask = (const int*)  d_in[1];
    const float* Wq   = (const float*)d_in[2];
    const float* bq   = (const float*)d_in[3];
    const float* Wk   = (const float*)d_in[4];
    const float* bk   = (const float*)d_in[5];
    const float* Wv   = (const float*)d_in[6];
    const float* bv   = (const float*)d_in[7];
    const float* Wo   = (const float*)d_in[8];
    const float* bo   = (const float*)d_in[9];
    float* out = (float*)d_out;

    float *q, *k, *v, *att;
    cudaGetSymbolAddress((void**)&q,   g_q);
    cudaGetSymbolAddress((void**)&k,   g_k);
    cudaGetSymbolAddress((void**)&v,   g_v);
    cudaGetSymbolAddress((void**)&att, g_att);

    cudaFuncSetAttribute(attn_tf32, cudaFuncAttributeMaxDynamicSharedMemorySize, SMEM_ATTN);

    dim3 thr(256);
    qkv_tf32<<<dim3(24, MROWS / TBM), thr>>>(x, Wq, bq, Wk, bk, Wv, bv, q, k, v);
    attn_tf32<<<dim3(SEQ / ABQ, BB * NHEAD), thr, SMEM_ATTN>>>(mask);
    oproj_tf32<<<dim3(DMODEL / TBN, MROWS / TBM), thr>>>(att, Wo, bo, out);
}